// round 3
// baseline (speedup 1.0000x reference)
#include <cuda_runtime.h>
#include <math.h>

// Problem constants (fixed by the dataset problem)
#define SEQ  2048
#define DIM  1024
#define NH   16
#define HD   64

// Scratch (device globals: no allocations allowed)
__device__ float g_q[SEQ * DIM];
__device__ float g_k[SEQ * DIM];
__device__ float g_v[SEQ * DIM];
__device__ float g_att[SEQ * DIM];
__device__ float g_cos[SEQ * 32];
__device__ float g_sin[SEQ * 32];

// ---------------------------------------------------------------------------
// RoPE table: replicate JAX fp32 pipeline (inv_freq rounded to fp32, angle =
// fp32(t)*fp32(inv_freq) rounded to fp32), then accurate trig on that fp32
// angle via double (matches XLA's accurate fp32 cos/sin incl. range reduction).
// ---------------------------------------------------------------------------
__global__ void rope_table_kernel() {
    int t = blockIdx.x;       // sequence position
    int i = threadIdx.x;      // 0..31 (rotary pair index)
    double p = pow(10000.0, (double)i / 32.0);
    float invf = 1.0f / (float)p;       // fp32 inv_freq (as reference does)
    float f = (float)t * invf;          // fp32 angle (as reference does)
    double fd = (double)f;
    g_cos[t * 32 + i] = (float)cos(fd);
    g_sin[t * 32 + i] = (float)sin(fd);
}

// ---------------------------------------------------------------------------
// NT GEMM: C[M,N] = A[M,K] @ B[N,K]^T   (all row-major, fp32)
// 64x64 tile, BK=32, 256 threads, 4x4 micro-tile per thread.
// ---------------------------------------------------------------------------
__global__ __launch_bounds__(256) void gemm_nt(const float* __restrict__ A,
                                               const float* __restrict__ B,
                                               float* __restrict__ C,
                                               int N, int K) {
    __shared__ float As[32][68];   // [k][m], pad 68 keeps 16B alignment
    __shared__ float Bs[32][68];   // [k][n]
    int tid = threadIdx.x;
    int tx = tid & 15, ty = tid >> 4;
    int bm = blockIdx.y * 64, bn = blockIdx.x * 64;
    int lr = tid >> 5;      // 0..7
    int lc = tid & 31;      // 0..31 (k index, coalesced)

    float acc[4][4];
#pragma unroll
    for (int i = 0; i < 4; i++)
#pragma unroll
        for (int j = 0; j < 4; j++) acc[i][j] = 0.f;

    for (int k0 = 0; k0 < K; k0 += 32) {
#pragma unroll
        for (int i = 0; i < 8; i++) {
            int r = lr + i * 8;
            As[lc][r] = A[(size_t)(bm + r) * K + k0 + lc];
            Bs[lc][r] = B[(size_t)(bn + r) * K + k0 + lc];
        }
        __syncthreads();
#pragma unroll
        for (int kk = 0; kk < 32; kk++) {
            float4 a4 = *(const float4*)&As[kk][ty * 4];
            float4 b4 = *(const float4*)&Bs[kk][tx * 4];
            float a[4] = {a4.x, a4.y, a4.z, a4.w};
            float b[4] = {b4.x, b4.y, b4.z, b4.w};
#pragma unroll
            for (int i = 0; i < 4; i++)
#pragma unroll
                for (int j = 0; j < 4; j++) acc[i][j] += a[i] * b[j];
        }
        __syncthreads();
    }
#pragma unroll
    for (int i = 0; i < 4; i++) {
        int row = bm + ty * 4 + i;
        float4 o4 = make_float4(acc[i][0], acc[i][1], acc[i][2], acc[i][3]);
        *(float4*)&C[(size_t)row * N + bn + tx * 4] = o4;
    }
}

// ---------------------------------------------------------------------------
// Post-process: V = (1-l)*V + l*v1 ; Q,K = rope(rmsnorm(.)) per (s,h) row.
// One warp per (s,h); lane owns dims {lane, lane+32}.
// ---------------------------------------------------------------------------
__global__ __launch_bounds__(256) void postproc_kernel(const float* __restrict__ v1,
                                                       const float* __restrict__ lam_p) {
    int warp = threadIdx.x >> 5, lane = threadIdx.x & 31;
    int row = blockIdx.x * 8 + warp;       // (s*NH + h)
    int s_idx = row >> 4;
    int h = row & 15;
    int base = s_idx * DIM + h * HD;
    float lam = *lam_p;

    // V blend
    {
        float a = g_v[base + lane], b = g_v[base + lane + 32];
        g_v[base + lane]      = (1.f - lam) * a + lam * v1[base + lane];
        g_v[base + lane + 32] = (1.f - lam) * b + lam * v1[base + lane + 32];
    }

    float c = g_cos[s_idx * 32 + lane];
    float sn = g_sin[s_idx * 32 + lane];
    const float eps = 1.1920928955078125e-07f;  // FLT_EPSILON == finfo(f32).eps

    // Q: rmsnorm + rope
    {
        float a = g_q[base + lane], b = g_q[base + lane + 32];
        float ss = a * a + b * b;
#pragma unroll
        for (int off = 16; off; off >>= 1) ss += __shfl_xor_sync(0xffffffffu, ss, off);
        float mean = ss * (1.f / 64.f) + eps;
        float r = rsqrtf(mean);
        r = r * (1.5f - 0.5f * mean * r * r);   // Newton refine
        a *= r; b *= r;
        g_q[base + lane]      = a * c + b * sn;
        g_q[base + lane + 32] = -a * sn + b * c;
    }
    // K: rmsnorm + rope
    {
        float a = g_k[base + lane], b = g_k[base + lane + 32];
        float ss = a * a + b * b;
#pragma unroll
        for (int off = 16; off; off >>= 1) ss += __shfl_xor_sync(0xffffffffu, ss, off);
        float mean = ss * (1.f / 64.f) + eps;
        float r = rsqrtf(mean);
        r = r * (1.5f - 0.5f * mean * r * r);
        a *= r; b *= r;
        g_k[base + lane]      = a * c + b * sn;
        g_k[base + lane + 32] = -a * sn + b * c;
    }
}

// ---------------------------------------------------------------------------
// Flash attention (fp32, causal). Block = one (q-tile of 64, head).
// 256 threads: quad (4 threads) per q row; thread g in quad owns k-cols
// {j*4+g} for scores and output dims [g*16, g*16+16).
// ---------------------------------------------------------------------------
#define FPAD 68
__global__ __launch_bounds__(256) void flash_kernel() {
    extern __shared__ float sm[];
    float* Qs = sm;                 // [64][FPAD]
    float* Ks = sm + 64 * FPAD;
    float* Vs = sm + 2 * 64 * FPAD;

    int h = blockIdx.y;
    int qt = blockIdx.x;
    int tid = threadIdx.x;
    int g = tid & 3;
    int qr = tid >> 2;              // 0..63 (q row in tile)
    int lane = tid & 31;
    int qbase = lane & ~3;

    // Load Q tile, pre-scaled by 1/sqrt(64)=0.125 (exact power of two)
#pragma unroll
    for (int i = 0; i < 4; i++) {
        int e = tid + i * 256;
        int r = e >> 4, c4 = e & 15;
        float4 t4 = *(const float4*)&g_q[(size_t)(qt * 64 + r) * DIM + h * HD + c4 * 4];
        t4.x *= 0.125f; t4.y *= 0.125f; t4.z *= 0.125f; t4.w *= 0.125f;
        *(float4*)&Qs[r * FPAD + c4 * 4] = t4;
    }

    float m = -1e30f, l = 0.f;
    float o[16];
#pragma unroll
    for (int d = 0; d < 16; d++) o[d] = 0.f;

    for (int kt = 0; kt <= qt; kt++) {
        __syncthreads();   // Qs ready (1st iter) / prior-iter reads done
#pragma unroll
        for (int i = 0; i < 4; i++) {
            int e = tid + i * 256;
            int r = e >> 4, c4 = e & 15;
            *(float4*)&Ks[r * FPAD + c4 * 4] =
                *(const float4*)&g_k[(size_t)(kt * 64 + r) * DIM + h * HD + c4 * 4];
            *(float4*)&Vs[r * FPAD + c4 * 4] =
                *(const float4*)&g_v[(size_t)(kt * 64 + r) * DIM + h * HD + c4 * 4];
        }
        __syncthreads();

        // Scores: s[j] = q[qr] . k[j*4+g]
        float s[16];
#pragma unroll
        for (int j = 0; j < 16; j++) s[j] = 0.f;
#pragma unroll
        for (int k4 = 0; k4 < 16; k4++) {
            float4 q4 = *(const float4*)&Qs[qr * FPAD + k4 * 4];
#pragma unroll
            for (int j = 0; j < 16; j++) {
                float4 kk = *(const float4*)&Ks[(j * 4 + g) * FPAD + k4 * 4];
                s[j] += q4.x * kk.x + q4.y * kk.y + q4.z * kk.z + q4.w * kk.w;
            }
        }

        // Causal mask (only diagonal tile needs it)
        if (kt == qt) {
#pragma unroll
            for (int j = 0; j < 16; j++)
                if (j * 4 + g > qr) s[j] = -1e30f;
        }

        // Online softmax (reduce across quad via xor-shuffles)
        float mloc = -1e30f;
#pragma unroll
        for (int j = 0; j < 16; j++) mloc = fmaxf(mloc, s[j]);
        mloc = fmaxf(mloc, __shfl_xor_sync(0xffffffffu, mloc, 1));
        mloc = fmaxf(mloc, __shfl_xor_sync(0xffffffffu, mloc, 2));
        float mnew = fmaxf(m, mloc);
        float alpha = __expf(m - mnew);
        float ladd = 0.f;
#pragma unroll
        for (int j = 0; j < 16; j++) {
            float p = __expf(s[j] - mnew);
            s[j] = p;
            ladd += p;
        }
        ladd += __shfl_xor_sync(0xffffffffu, ladd, 1);
        ladd += __shfl_xor_sync(0xffffffffu, ladd, 2);
        l = l * alpha + ladd;
        m = mnew;
#pragma unroll
        for (int d = 0; d < 16; d++) o[d] *= alpha;

        // o[g*16+dd] += p[qr][kc] * V[kc][g*16+dd], p fetched from quad lanes
#pragma unroll
        for (int g2 = 0; g2 < 4; g2++) {
#pragma unroll
            for (int j = 0; j < 16; j++) {
                float p = __shfl_sync(0xffffffffu, s[j], qbase | g2);
                const float* vr = &Vs[(j * 4 + g2) * FPAD + g * 16];
                float4 v0 = *(const float4*)&vr[0];
                float4 v1r = *(const float4*)&vr[4];
                float4 v2r = *(const float4*)&vr[8];
                float4 v3r = *(const float4*)&vr[12];
                o[0]  += p * v0.x;  o[1]  += p * v0.y;  o[2]  += p * v0.z;  o[3]  += p * v0.w;
                o[4]  += p * v1r.x; o[5]  += p * v1r.y; o[6]  += p * v1r.z; o[7]  += p * v1r.w;
                o[8]  += p * v2r.x; o[9]  += p * v2r.y; o[10] += p * v2r.z; o[11] += p * v2r.w;
                o[12] += p * v3r.x; o[13] += p * v3r.y; o[14] += p * v3r.z; o[15] += p * v3r.w;
            }
        }
    }

    float inv = 1.f / l;
    size_t ob = (size_t)(qt * 64 + qr) * DIM + h * HD + g * 16;
#pragma unroll
    for (int d4 = 0; d4 < 4; d4++) {
        float4 w4 = make_float4(o[d4 * 4] * inv, o[d4 * 4 + 1] * inv,
                                o[d4 * 4 + 2] * inv, o[d4 * 4 + 3] * inv);
        *(float4*)&g_att[ob + d4 * 4] = w4;
    }
}

// v1 passthrough copy
__global__ void copy_kernel(const float4* __restrict__ src, float4* __restrict__ dst, int n4) {
    int i = blockIdx.x * blockDim.x + threadIdx.x;
    if (i < n4) dst[i] = src[i];
}

// ---------------------------------------------------------------------------
extern "C" void kernel_launch(void* const* d_in, const int* in_sizes, int n_in,
                              void* d_out, int out_size) {
    const float* x    = (const float*)d_in[0];
    const float* v1   = (const float*)d_in[1];
    const float* Wq   = (const float*)d_in[2];
    const float* Wk   = (const float*)d_in[3];
    const float* Wv   = (const float*)d_in[4];
    const float* Wout = (const float*)d_in[5];
    const float* lam  = (const float*)d_in[6];
    float* out = (float*)d_out;

    float *q, *k, *v, *att;
    cudaGetSymbolAddress((void**)&q, g_q);
    cudaGetSymbolAddress((void**)&k, g_k);
    cudaGetSymbolAddress((void**)&v, g_v);
    cudaGetSymbolAddress((void**)&att, g_att);

    rope_table_kernel<<<SEQ, 32>>>();

    dim3 gg(DIM / 64, SEQ / 64);
    gemm_nt<<<gg, 256>>>(x, Wq, q, DIM, DIM);
    gemm_nt<<<gg, 256>>>(x, Wk, k, DIM, DIM);
    gemm_nt<<<gg, 256>>>(x, Wv, v, DIM, DIM);

    postproc_kernel<<<(SEQ * NH) / 8, 256>>>(v1, lam);

    int flash_smem = 3 * 64 * FPAD * (int)sizeof(float);   // ~52 KB
    cudaFuncSetAttribute(flash_kernel, cudaFuncAttributeMaxDynamicSharedMemorySize,
                         flash_smem);
    flash_kernel<<<dim3(SEQ / 64, NH), 256, flash_smem>>>();

    gemm_nt<<<gg, 256>>>(att, Wout, out, DIM, DIM);

    if (out_size >= 2 * SEQ * DIM) {
        int n4 = (SEQ * DIM) / 4;
        copy_kernel<<<(n4 + 255) / 256, 256>>>((const float4*)v1,
                                               (float4*)(out + SEQ * DIM), n4);
    }
}

// round 4
// speedup vs baseline: 1.9107x; 1.9107x over previous
#include <cuda_runtime.h>
#include <math.h>

// Problem constants (fixed by the dataset problem)
#define SEQ  2048
#define DIM  1024
#define NH   16
#define HD   64

// Scratch (device globals: no allocations allowed)
__device__ float g_q[SEQ * DIM];
__device__ float g_k[SEQ * DIM];
__device__ float g_v[SEQ * DIM];
__device__ float g_att[SEQ * DIM];
__device__ float g_cos[SEQ * 32];
__device__ float g_sin[SEQ * 32];

// ---------------------------------------------------------------------------
// RoPE table (matches JAX fp32 pipeline; accurate trig via double on the
// fp32-rounded angle).
// ---------------------------------------------------------------------------
__global__ void rope_table_kernel() {
    int t = blockIdx.x;
    int i = threadIdx.x;      // 0..31
    double p = pow(10000.0, (double)i / 32.0);
    float invf = 1.0f / (float)p;
    float f = (float)t * invf;
    double fd = (double)f;
    g_cos[t * 32 + i] = (float)cos(fd);
    g_sin[t * 32 + i] = (float)sin(fd);
}

// ---------------------------------------------------------------------------
// NT GEMM: C[M,N] = A[M,K] @ B[N,K]^T  (near fp32-FFMA roofline; unchanged)
// ---------------------------------------------------------------------------
__global__ __launch_bounds__(256) void gemm_nt(const float* __restrict__ A,
                                               const float* __restrict__ B,
                                               float* __restrict__ C,
                                               int N, int K) {
    __shared__ float As[32][68];
    __shared__ float Bs[32][68];
    int tid = threadIdx.x;
    int tx = tid & 15, ty = tid >> 4;
    int bm = blockIdx.y * 64, bn = blockIdx.x * 64;
    int lr = tid >> 5;
    int lc = tid & 31;

    float acc[4][4];
#pragma unroll
    for (int i = 0; i < 4; i++)
#pragma unroll
        for (int j = 0; j < 4; j++) acc[i][j] = 0.f;

    for (int k0 = 0; k0 < K; k0 += 32) {
#pragma unroll
        for (int i = 0; i < 8; i++) {
            int r = lr + i * 8;
            As[lc][r] = A[(size_t)(bm + r) * K + k0 + lc];
            Bs[lc][r] = B[(size_t)(bn + r) * K + k0 + lc];
        }
        __syncthreads();
#pragma unroll
        for (int kk = 0; kk < 32; kk++) {
            float4 a4 = *(const float4*)&As[kk][ty * 4];
            float4 b4 = *(const float4*)&Bs[kk][tx * 4];
            float a[4] = {a4.x, a4.y, a4.z, a4.w};
            float b[4] = {b4.x, b4.y, b4.z, b4.w};
#pragma unroll
            for (int i = 0; i < 4; i++)
#pragma unroll
                for (int j = 0; j < 4; j++) acc[i][j] += a[i] * b[j];
        }
        __syncthreads();
    }
#pragma unroll
    for (int i = 0; i < 4; i++) {
        int row = bm + ty * 4 + i;
        float4 o4 = make_float4(acc[i][0], acc[i][1], acc[i][2], acc[i][3]);
        *(float4*)&C[(size_t)row * N + bn + tx * 4] = o4;
    }
}

// ---------------------------------------------------------------------------
// Post-process: V blend, rmsnorm+rope on Q/K. (unchanged)
// ---------------------------------------------------------------------------
__global__ __launch_bounds__(256) void postproc_kernel(const float* __restrict__ v1,
                                                       const float* __restrict__ lam_p) {
    int warp = threadIdx.x >> 5, lane = threadIdx.x & 31;
    int row = blockIdx.x * 8 + warp;
    int s_idx = row >> 4;
    int h = row & 15;
    int base = s_idx * DIM + h * HD;
    float lam = *lam_p;

    {
        float a = g_v[base + lane], b = g_v[base + lane + 32];
        g_v[base + lane]      = (1.f - lam) * a + lam * v1[base + lane];
        g_v[base + lane + 32] = (1.f - lam) * b + lam * v1[base + lane + 32];
    }

    float c = g_cos[s_idx * 32 + lane];
    float sn = g_sin[s_idx * 32 + lane];
    const float eps = 1.1920928955078125e-07f;

    {
        float a = g_q[base + lane], b = g_q[base + lane + 32];
        float ss = a * a + b * b;
#pragma unroll
        for (int off = 16; off; off >>= 1) ss += __shfl_xor_sync(0xffffffffu, ss, off);
        float mean = ss * (1.f / 64.f) + eps;
        float r = rsqrtf(mean);
        r = r * (1.5f - 0.5f * mean * r * r);
        a *= r; b *= r;
        g_q[base + lane]      = a * c + b * sn;
        g_q[base + lane + 32] = -a * sn + b * c;
    }
    {
        float a = g_k[base + lane], b = g_k[base + lane + 32];
        float ss = a * a + b * b;
#pragma unroll
        for (int off = 16; off; off >>= 1) ss += __shfl_xor_sync(0xffffffffu, ss, off);
        float mean = ss * (1.f / 64.f) + eps;
        float r = rsqrtf(mean);
        r = r * (1.5f - 0.5f * mean * r * r);
        a *= r; b *= r;
        g_k[base + lane]      = a * c + b * sn;
        g_k[base + lane + 32] = -a * sn + b * c;
    }
}

// ---------------------------------------------------------------------------
// Flash attention v2 (fp32, causal), register-tiled outer-product style.
// Block = (128 q rows, head). 256 threads = 16(tx) x 16(ty).
// Thread (ty,tx): q rows ty*8..ty*8+7.
//   QK : k cols {tx, 16+tx, 32+tx, 48+tx}  -> s[8][4]
//   PV : d cols {tx, 16+tx, 32+tx, 48+tx}  -> o[8][4], P staged in smem
//        k-major (q contiguous) so p loads are broadcasts.
// Row-stat reductions across the 16 tx lanes via xor-shuffles (1,2,4,8).
// ---------------------------------------------------------------------------
#define FH 68    // Q/K/V smem row stride (floats)
#define FP 132   // P  smem row stride (floats)

__global__ __launch_bounds__(256) void flash_kernel() {
    extern __shared__ float sm[];
    float* Qs = sm;                        // [128][FH]
    float* Ks = Qs + 128 * FH;             // [64][FH]
    float* Vs = Ks + 64 * FH;              // [64][FH]
    float* Ps = Vs + 64 * FH;              // [64][FP]  k-major

    int h  = blockIdx.x;
    int qt = 15 - (int)blockIdx.y;         // LPT: heavy tiles first
    int tid = threadIdx.x;
    int tx = tid & 15;
    int ty = tid >> 4;

    int q0 = qt * 128;

    // Load Q tile, pre-scaled by 1/sqrt(64) = 0.125 (exact)
#pragma unroll
    for (int i = 0; i < 8; i++) {
        int e = tid + i * 256;             // 0..2047
        int r = e >> 4, c4 = e & 15;
        float4 t = *(const float4*)&g_q[(size_t)(q0 + r) * DIM + h * HD + c4 * 4];
        t.x *= 0.125f; t.y *= 0.125f; t.z *= 0.125f; t.w *= 0.125f;
        *(float4*)&Qs[r * FH + c4 * 4] = t;
    }

    float m[8], l[8], o[8][4];
#pragma unroll
    for (int i = 0; i < 8; i++) {
        m[i] = -1e30f; l[i] = 0.f;
#pragma unroll
        for (int j = 0; j < 4; j++) o[i][j] = 0.f;
    }

    int nkt = 2 * qt + 2;
    for (int kt = 0; kt < nkt; kt++) {
        __syncthreads();                   // prior PV reads done (and Q stores on iter 0 pre-pass)
        // Load K, V tiles (64 x 64)
#pragma unroll
        for (int i = 0; i < 4; i++) {
            int e = tid + i * 256;
            int r = e >> 4, c4 = e & 15;
            *(float4*)&Ks[r * FH + c4 * 4] =
                *(const float4*)&g_k[(size_t)(kt * 64 + r) * DIM + h * HD + c4 * 4];
            *(float4*)&Vs[r * FH + c4 * 4] =
                *(const float4*)&g_v[(size_t)(kt * 64 + r) * DIM + h * HD + c4 * 4];
        }
        __syncthreads();

        // ---- QK: s[i][j] = q(ty*8+i) . k(j*16+tx) ----
        float s[8][4];
#pragma unroll
        for (int i = 0; i < 8; i++)
#pragma unroll
            for (int j = 0; j < 4; j++) s[i][j] = 0.f;

#pragma unroll
        for (int d4 = 0; d4 < 16; d4++) {
            float4 k4[4];
#pragma unroll
            for (int j = 0; j < 4; j++)
                k4[j] = *(const float4*)&Ks[(j * 16 + tx) * FH + d4 * 4];
#pragma unroll
            for (int i = 0; i < 8; i++) {
                float4 q4 = *(const float4*)&Qs[(ty * 8 + i) * FH + d4 * 4];
#pragma unroll
                for (int j = 0; j < 4; j++) {
                    s[i][j] += q4.x * k4[j].x + q4.y * k4[j].y
                             + q4.z * k4[j].z + q4.w * k4[j].w;
                }
            }
        }

        // Causal mask — only the last two k-tiles can cross the diagonal
        if (kt >= 2 * qt) {
#pragma unroll
            for (int i = 0; i < 8; i++) {
                int grow = q0 + ty * 8 + i;
#pragma unroll
                for (int j = 0; j < 4; j++)
                    if (kt * 64 + j * 16 + tx > grow) s[i][j] = -1e30f;
            }
        }

        // ---- Online softmax (per q row; reduce across 16 tx lanes) ----
#pragma unroll
        for (int i = 0; i < 8; i++) {
            float mloc = fmaxf(fmaxf(s[i][0], s[i][1]), fmaxf(s[i][2], s[i][3]));
            mloc = fmaxf(mloc, __shfl_xor_sync(0xffffffffu, mloc, 1));
            mloc = fmaxf(mloc, __shfl_xor_sync(0xffffffffu, mloc, 2));
            mloc = fmaxf(mloc, __shfl_xor_sync(0xffffffffu, mloc, 4));
            mloc = fmaxf(mloc, __shfl_xor_sync(0xffffffffu, mloc, 8));
            float mnew = fmaxf(m[i], mloc);
            float alpha = __expf(m[i] - mnew);
            float sum = 0.f;
#pragma unroll
            for (int j = 0; j < 4; j++) {
                float p = __expf(s[i][j] - mnew);
                s[i][j] = p;
                sum += p;
            }
            sum += __shfl_xor_sync(0xffffffffu, sum, 1);
            sum += __shfl_xor_sync(0xffffffffu, sum, 2);
            sum += __shfl_xor_sync(0xffffffffu, sum, 4);
            sum += __shfl_xor_sync(0xffffffffu, sum, 8);
            l[i] = l[i] * alpha + sum;
            m[i] = mnew;
#pragma unroll
            for (int j = 0; j < 4; j++) o[i][j] *= alpha;
        }

        // Stage P k-major (q contiguous)
#pragma unroll
        for (int i = 0; i < 8; i++)
#pragma unroll
            for (int j = 0; j < 4; j++)
                Ps[(j * 16 + tx) * FP + ty * 8 + i] = s[i][j];
        __syncthreads();

        // ---- PV: o[i][mc] += P[kk][ty*8+i] * V[kk][mc*16+tx] ----
#pragma unroll 4
        for (int kk = 0; kk < 64; kk++) {
            float4 pa = *(const float4*)&Ps[kk * FP + ty * 8];
            float4 pb = *(const float4*)&Ps[kk * FP + ty * 8 + 4];
            float vv[4];
#pragma unroll
            for (int mc = 0; mc < 4; mc++) vv[mc] = Vs[kk * FH + mc * 16 + tx];
            float pr[8] = {pa.x, pa.y, pa.z, pa.w, pb.x, pb.y, pb.z, pb.w};
#pragma unroll
            for (int i = 0; i < 8; i++)
#pragma unroll
                for (int mc = 0; mc < 4; mc++) o[i][mc] += pr[i] * vv[mc];
        }
    }

    // Normalize and write out
#pragma unroll
    for (int i = 0; i < 8; i++) {
        float inv = 1.f / l[i];
        size_t rb = (size_t)(q0 + ty * 8 + i) * DIM + h * HD;
#pragma unroll
        for (int mc = 0; mc < 4; mc++)
            g_att[rb + mc * 16 + tx] = o[i][mc] * inv;
    }
}

// v1 passthrough copy
__global__ void copy_kernel(const float4* __restrict__ src, float4* __restrict__ dst, int n4) {
    int i = blockIdx.x * blockDim.x + threadIdx.x;
    if (i < n4) dst[i] = src[i];
}

// ---------------------------------------------------------------------------
extern "C" void kernel_launch(void* const* d_in, const int* in_sizes, int n_in,
                              void* d_out, int out_size) {
    const float* x    = (const float*)d_in[0];
    const float* v1   = (const float*)d_in[1];
    const float* Wq   = (const float*)d_in[2];
    const float* Wk   = (const float*)d_in[3];
    const float* Wv   = (const float*)d_in[4];
    const float* Wout = (const float*)d_in[5];
    const float* lam  = (const float*)d_in[6];
    float* out = (float*)d_out;

    float *q, *k, *v, *att;
    cudaGetSymbolAddress((void**)&q, g_q);
    cudaGetSymbolAddress((void**)&k, g_k);
    cudaGetSymbolAddress((void**)&v, g_v);
    cudaGetSymbolAddress((void**)&att, g_att);

    rope_table_kernel<<<SEQ, 32>>>();

    dim3 gg(DIM / 64, SEQ / 64);
    gemm_nt<<<gg, 256>>>(x, Wq, q, DIM, DIM);
    gemm_nt<<<gg, 256>>>(x, Wk, k, DIM, DIM);
    gemm_nt<<<gg, 256>>>(x, Wv, v, DIM, DIM);

    postproc_kernel<<<(SEQ * NH) / 8, 256>>>(v1, lam);

    int flash_smem = (128 * FH + 64 * FH + 64 * FH + 64 * FP) * (int)sizeof(float);
    cudaFuncSetAttribute(flash_kernel, cudaFuncAttributeMaxDynamicSharedMemorySize,
                         flash_smem);
    flash_kernel<<<dim3(NH, SEQ / 128), 256, flash_smem>>>();

    gemm_nt<<<gg, 256>>>(att, Wout, out, DIM, DIM);

    if (out_size >= 2 * SEQ * DIM) {
        int n4 = (SEQ * DIM) / 4;
        copy_kernel<<<(n4 + 255) / 256, 256>>>((const float4*)v1,
                                               (float4*)(out + SEQ * DIM), n4);
    }
}

// round 6
// speedup vs baseline: 3.5650x; 1.8658x over previous
#include <cuda_runtime.h>
#include <cuda_bf16.h>
#include <math.h>
#include <stdint.h>

// Problem constants
#define SEQ  2048
#define DIM  1024
#define NH   16
#define HD   64
#define KE   3072      // split-bf16 effective K (3 x 1024)

// Scratch (device globals; allocations are forbidden)
__device__ float g_q[SEQ * DIM];
__device__ float g_k[SEQ * DIM];
__device__ float g_v[SEQ * DIM];
__device__ float g_att[SEQ * DIM];
__device__ float g_cos[SEQ * 32];
__device__ float g_sin[SEQ * 32];
__device__ __nv_bfloat16 g_abig[SEQ * KE];        // [Ah|Ah|Al] for x / att
__device__ __nv_bfloat16 g_wbig[4][DIM * KE];     // [Wh|Wl|Wh] per weight

// ===========================================================================
// Arch-generic tensor-core helpers (sm_80+; compile on bare sm_103 target)
// ===========================================================================
__device__ __forceinline__ uint32_t smem_u32(const void* p) {
    uint32_t a;
    asm("{ .reg .u64 t; cvta.to.shared.u64 t, %1; cvt.u32.u64 %0, t; }"
        : "=r"(a) : "l"(p));
    return a;
}
__device__ __forceinline__ void ldsm_x4(uint32_t* r, uint32_t addr) {
    asm volatile("ldmatrix.sync.aligned.m8n8.x4.shared.b16 {%0,%1,%2,%3}, [%4];"
                 : "=r"(r[0]), "=r"(r[1]), "=r"(r[2]), "=r"(r[3]) : "r"(addr));
}
__device__ __forceinline__ void mma16816(float* d, const uint32_t* a, const uint32_t* b) {
    asm volatile("mma.sync.aligned.m16n8k16.row.col.f32.bf16.bf16.f32 "
                 "{%0,%1,%2,%3}, {%4,%5,%6,%7}, {%8,%9}, {%0,%1,%2,%3};"
                 : "+f"(d[0]), "+f"(d[1]), "+f"(d[2]), "+f"(d[3])
                 : "r"(a[0]), "r"(a[1]), "r"(a[2]), "r"(a[3]),
                   "r"(b[0]), "r"(b[1]));
}
__device__ __forceinline__ void cp_async16(uint32_t dst, const void* src) {
    asm volatile("cp.async.cg.shared.global [%0], [%1], 16;" :: "r"(dst), "l"(src));
}
#define CP_COMMIT() asm volatile("cp.async.commit_group;" ::: "memory")
#define CP_WAIT(n)  asm volatile("cp.async.wait_group %0;" :: "n"(n) : "memory")

__device__ __forceinline__ uint32_t sw128(uint32_t off) {
    return off ^ ((off >> 3) & 0x70);
}

// ===========================================================================
// RoPE table
// ===========================================================================
__global__ void rope_table_kernel() {
    int t = blockIdx.x;
    int i = threadIdx.x;
    double p = pow(10000.0, (double)i / 32.0);
    float invf = 1.0f / (float)p;
    float f = (float)t * invf;
    double fd = (double)f;
    g_cos[t * 32 + i] = (float)cos(fd);
    g_sin[t * 32 + i] = (float)sin(fd);
}

// ===========================================================================
// Split fp32 -> (hi, lo) bf16 triples.
// modeA=1: dst row = [H | H | L]  (activations)
// modeA=0: dst row = [H | L | H]  (weights)
// ===========================================================================
__global__ __launch_bounds__(256) void split_bf16_kernel(const float* __restrict__ src,
                                                         __nv_bfloat16* __restrict__ dst,
                                                         int modeA) {
    int idx = blockIdx.x * 256 + threadIdx.x;
    int r = idx >> 10, c = idx & 1023;
    float x = src[idx];
    __nv_bfloat16 h = __float2bfloat16(x);
    float hf = __bfloat162float(h);
    __nv_bfloat16 l = __float2bfloat16(x - hf);
    size_t b = (size_t)r * KE + c;
    dst[b] = h;
    if (modeA) { dst[b + 1024] = h; dst[b + 2048] = l; }
    else       { dst[b + 1024] = l; dst[b + 2048] = h; }
}

// ===========================================================================
// HMMA NT GEMM: C[2048,1024] fp32 = A'[2048,KE] @ B'[1024,KE]^T
// CTA tile 128x128, 8 warps (warp tile 64x32), K-chunk 64 bf16,
// SW128-swizzled smem, double-buffered cp.async.
// ===========================================================================
#define TM 128
#define TN 128
#define KC 64
#define NCH (KE / KC)              // 48
#define ASZ (TM * 128)             // 16 KB per A buffer (128B-wide rows)
#define BSZ (TN * 128)
#define GSMEM (2 * (ASZ + BSZ))    // 64 KB

__device__ __forceinline__ void g_load_chunk(uint32_t sb, int buf,
                                             const char* Ag, const char* Bg,
                                             int c, int tid) {
    uint32_t ab = sb + buf * (ASZ + BSZ);
    uint32_t bb = ab + ASZ;
    size_t coff = (size_t)c * 128;        // byte offset within a KE-row
#pragma unroll
    for (int i = 0; i < 4; i++) {          // A: 128 rows x 8 segs of 16B
        int u = tid + i * 256;
        int row = u >> 3, seg = u & 7;
        uint32_t off = row * 128 + seg * 16;
        cp_async16(ab + sw128(off), Ag + (size_t)row * (KE * 2) + coff + seg * 16);
    }
#pragma unroll
    for (int i = 0; i < 4; i++) {          // B: 128 rows
        int u = tid + i * 256;
        int row = u >> 3, seg = u & 7;
        uint32_t off = row * 128 + seg * 16;
        cp_async16(bb + sw128(off), Bg + (size_t)row * (KE * 2) + coff + seg * 16);
    }
}

__global__ __launch_bounds__(256) void gemm_hmma(const __nv_bfloat16* __restrict__ A,
                                                 const __nv_bfloat16* __restrict__ B,
                                                 float* __restrict__ C) {
    extern __shared__ __align__(128) char smem[];
    uint32_t sb = smem_u32(smem);
    int tid = threadIdx.x;
    int wid = tid >> 5, lane = tid & 31;
    int wm = wid & 1, wn = wid >> 1;      // warp tile: (wm*64, wn*32)
    int bm = blockIdx.y * TM, bn = blockIdx.x * TN;

    const char* Ag = (const char*)(A + (size_t)bm * KE);
    const char* Bg = (const char*)(B + (size_t)bn * KE);

    float acc[4][4][4];
#pragma unroll
    for (int mt = 0; mt < 4; mt++)
#pragma unroll
        for (int nt = 0; nt < 4; nt++)
#pragma unroll
            for (int r = 0; r < 4; r++) acc[mt][nt][r] = 0.f;

    g_load_chunk(sb, 0, Ag, Bg, 0, tid);
    CP_COMMIT();

    // precomputed per-lane fragment row indices
    int a_row = wm * 64 + (lane & 15);           // + mt*16
    int a_kb  = (lane >> 4) * 16;                // byte offset within k16 step
    int b_row = wn * 32 + (lane & 7) + ((lane >> 4) << 3);   // + bt*16
    int b_kb  = ((lane >> 3) & 1) * 16;

    for (int c = 0; c < NCH; c++) {
        int buf = c & 1;
        if (c + 1 < NCH) {
            g_load_chunk(sb, buf ^ 1, Ag, Bg, c + 1, tid);
            CP_COMMIT();
            CP_WAIT(1);
        } else {
            CP_WAIT(0);
        }
        __syncthreads();

        uint32_t abase = sb + buf * (ASZ + BSZ);
        uint32_t bbase = abase + ASZ;
#pragma unroll
        for (int ks = 0; ks < 4; ks++) {
            uint32_t af[4][4];
#pragma unroll
            for (int mt = 0; mt < 4; mt++) {
                uint32_t off = (a_row + mt * 16) * 128 + ks * 32 + a_kb;
                ldsm_x4(af[mt], abase + sw128(off));
            }
            uint32_t bf[2][4];
#pragma unroll
            for (int bt = 0; bt < 2; bt++) {
                uint32_t off = (b_row + bt * 16) * 128 + ks * 32 + b_kb;
                ldsm_x4(bf[bt], bbase + sw128(off));
            }
#pragma unroll
            for (int mt = 0; mt < 4; mt++)
#pragma unroll
                for (int nt = 0; nt < 4; nt++)
                    mma16816(acc[mt][nt], af[mt], &bf[nt >> 1][(nt & 1) * 2]);
        }
        __syncthreads();
    }

    // Epilogue: write accumulators
    int g = lane >> 2, cp = (lane & 3) * 2;
#pragma unroll
    for (int mt = 0; mt < 4; mt++) {
#pragma unroll
        for (int nt = 0; nt < 4; nt++) {
            int row = bm + wm * 64 + mt * 16 + g;
            int col = bn + wn * 32 + nt * 8 + cp;
            float2 v0 = make_float2(acc[mt][nt][0], acc[mt][nt][1]);
            float2 v1 = make_float2(acc[mt][nt][2], acc[mt][nt][3]);
            *(float2*)&C[(size_t)row * DIM + col] = v0;
            *(float2*)&C[(size_t)(row + 8) * DIM + col] = v1;
        }
    }
}

// ===========================================================================
// Post-process: V blend, rmsnorm+rope on Q/K.
// ===========================================================================
__global__ __launch_bounds__(256) void postproc_kernel(const float* __restrict__ v1,
                                                       const float* __restrict__ lam_p) {
    int warp = threadIdx.x >> 5, lane = threadIdx.x & 31;
    int row = blockIdx.x * 8 + warp;
    int s_idx = row >> 4;
    int h = row & 15;
    int base = s_idx * DIM + h * HD;
    float lam = *lam_p;

    {
        float a = g_v[base + lane], b = g_v[base + lane + 32];
        g_v[base + lane]      = (1.f - lam) * a + lam * v1[base + lane];
        g_v[base + lane + 32] = (1.f - lam) * b + lam * v1[base + lane + 32];
    }
    float c = g_cos[s_idx * 32 + lane];
    float sn = g_sin[s_idx * 32 + lane];
    const float eps = 1.1920928955078125e-07f;
    {
        float a = g_q[base + lane], b = g_q[base + lane + 32];
        float ss = a * a + b * b;
#pragma unroll
        for (int off = 16; off; off >>= 1) ss += __shfl_xor_sync(0xffffffffu, ss, off);
        float mean = ss * (1.f / 64.f) + eps;
        float r = rsqrtf(mean);
        r = r * (1.5f - 0.5f * mean * r * r);
        a *= r; b *= r;
        g_q[base + lane]      = a * c + b * sn;
        g_q[base + lane + 32] = -a * sn + b * c;
    }
    {
        float a = g_k[base + lane], b = g_k[base + lane + 32];
        float ss = a * a + b * b;
#pragma unroll
        for (int off = 16; off; off >>= 1) ss += __shfl_xor_sync(0xffffffffu, ss, off);
        float mean = ss * (1.f / 64.f) + eps;
        float r = rsqrtf(mean);
        r = r * (1.5f - 0.5f * mean * r * r);
        a *= r; b *= r;
        g_k[base + lane]      = a * c + b * sn;
        g_k[base + lane + 32] = -a * sn + b * c;
    }
}

// ===========================================================================
// Flash attention v2 (fp32, causal) — unchanged from R4 (proven 260us)
// ===========================================================================
#define FH 68
#define FP 132

__global__ __launch_bounds__(256) void flash_kernel() {
    extern __shared__ float sm[];
    float* Qs = sm;
    float* Ks = Qs + 128 * FH;
    float* Vs = Ks + 64 * FH;
    float* Ps = Vs + 64 * FH;

    int h  = blockIdx.x;
    int qt = 15 - (int)blockIdx.y;
    int tid = threadIdx.x;
    int tx = tid & 15;
    int ty = tid >> 4;
    int q0 = qt * 128;

#pragma unroll
    for (int i = 0; i < 8; i++) {
        int e = tid + i * 256;
        int r = e >> 4, c4 = e & 15;
        float4 t = *(const float4*)&g_q[(size_t)(q0 + r) * DIM + h * HD + c4 * 4];
        t.x *= 0.125f; t.y *= 0.125f; t.z *= 0.125f; t.w *= 0.125f;
        *(float4*)&Qs[r * FH + c4 * 4] = t;
    }

    float m[8], l[8], o[8][4];
#pragma unroll
    for (int i = 0; i < 8; i++) {
        m[i] = -1e30f; l[i] = 0.f;
#pragma unroll
        for (int j = 0; j < 4; j++) o[i][j] = 0.f;
    }

    int nkt = 2 * qt + 2;
    for (int kt = 0; kt < nkt; kt++) {
        __syncthreads();
#pragma unroll
        for (int i = 0; i < 4; i++) {
            int e = tid + i * 256;
            int r = e >> 4, c4 = e & 15;
            *(float4*)&Ks[r * FH + c4 * 4] =
                *(const float4*)&g_k[(size_t)(kt * 64 + r) * DIM + h * HD + c4 * 4];
            *(float4*)&Vs[r * FH + c4 * 4] =
                *(const float4*)&g_v[(size_t)(kt * 64 + r) * DIM + h * HD + c4 * 4];
        }
        __syncthreads();

        float s[8][4];
#pragma unroll
        for (int i = 0; i < 8; i++)
#pragma unroll
            for (int j = 0; j < 4; j++) s[i][j] = 0.f;

#pragma unroll
        for (int d4 = 0; d4 < 16; d4++) {
            float4 k4[4];
#pragma unroll
            for (int j = 0; j < 4; j++)
                k4[j] = *(const float4*)&Ks[(j * 16 + tx) * FH + d4 * 4];
#pragma unroll
            for (int i = 0; i < 8; i++) {
                float4 q4 = *(const float4*)&Qs[(ty * 8 + i) * FH + d4 * 4];
#pragma unroll
                for (int j = 0; j < 4; j++) {
                    s[i][j] += q4.x * k4[j].x + q4.y * k4[j].y
                             + q4.z * k4[j].z + q4.w * k4[j].w;
                }
            }
        }

        if (kt >= 2 * qt) {
#pragma unroll
            for (int i = 0; i < 8; i++) {
                int grow = q0 + ty * 8 + i;
#pragma unroll
                for (int j = 0; j < 4; j++)
                    if (kt * 64 + j * 16 + tx > grow) s[i][j] = -1e30f;
            }
        }

#pragma unroll
        for (int i = 0; i < 8; i++) {
            float mloc = fmaxf(fmaxf(s[i][0], s[i][1]), fmaxf(s[i][2], s[i][3]));
            mloc = fmaxf(mloc, __shfl_xor_sync(0xffffffffu, mloc, 1));
            mloc = fmaxf(mloc, __shfl_xor_sync(0xffffffffu, mloc, 2));
            mloc = fmaxf(mloc, __shfl_xor_sync(0xffffffffu, mloc, 4));
            mloc = fmaxf(mloc, __shfl_xor_sync(0xffffffffu, mloc, 8));
            float mnew = fmaxf(m[i], mloc);
            float alpha = __expf(m[i] - mnew);
            float sum = 0.f;
#pragma unroll
            for (int j = 0; j < 4; j++) {
                float p = __expf(s[i][j] - mnew);
                s[i][j] = p;
                sum += p;
            }
            sum += __shfl_xor_sync(0xffffffffu, sum, 1);
            sum += __shfl_xor_sync(0xffffffffu, sum, 2);
            sum += __shfl_xor_sync(0xffffffffu, sum, 4);
            sum += __shfl_xor_sync(0xffffffffu, sum, 8);
            l[i] = l[i] * alpha + sum;
            m[i] = mnew;
#pragma unroll
            for (int j = 0; j < 4; j++) o[i][j] *= alpha;
        }

#pragma unroll
        for (int i = 0; i < 8; i++)
#pragma unroll
            for (int j = 0; j < 4; j++)
                Ps[(j * 16 + tx) * FP + ty * 8 + i] = s[i][j];
        __syncthreads();

#pragma unroll 4
        for (int kk = 0; kk < 64; kk++) {
            float4 pa = *(const float4*)&Ps[kk * FP + ty * 8];
            float4 pb = *(const float4*)&Ps[kk * FP + ty * 8 + 4];
            float vv[4];
#pragma unroll
            for (int mc = 0; mc < 4; mc++) vv[mc] = Vs[kk * FH + mc * 16 + tx];
            float pr[8] = {pa.x, pa.y, pa.z, pa.w, pb.x, pb.y, pb.z, pb.w};
#pragma unroll
            for (int i = 0; i < 8; i++)
#pragma unroll
                for (int mc = 0; mc < 4; mc++) o[i][mc] += pr[i] * vv[mc];
        }
    }

#pragma unroll
    for (int i = 0; i < 8; i++) {
        float inv = 1.f / l[i];
        size_t rb = (size_t)(q0 + ty * 8 + i) * DIM + h * HD;
#pragma unroll
        for (int mc = 0; mc < 4; mc++)
            g_att[rb + mc * 16 + tx] = o[i][mc] * inv;
    }
}

// v1 passthrough copy
__global__ void copy_kernel(const float4* __restrict__ src, float4* __restrict__ dst, int n4) {
    int i = blockIdx.x * blockDim.x + threadIdx.x;
    if (i < n4) dst[i] = src[i];
}

// ===========================================================================
extern "C" void kernel_launch(void* const* d_in, const int* in_sizes, int n_in,
                              void* d_out, int out_size) {
    const float* x    = (const float*)d_in[0];
    const float* v1   = (const float*)d_in[1];
    const float* Wq   = (const float*)d_in[2];
    const float* Wk   = (const float*)d_in[3];
    const float* Wv   = (const float*)d_in[4];
    const float* Wout = (const float*)d_in[5];
    const float* lam  = (const float*)d_in[6];
    float* out = (float*)d_out;

    float *q, *k, *v, *att;
    __nv_bfloat16 *abig, *wbig;
    cudaGetSymbolAddress((void**)&q, g_q);
    cudaGetSymbolAddress((void**)&k, g_k);
    cudaGetSymbolAddress((void**)&v, g_v);
    cudaGetSymbolAddress((void**)&att, g_att);
    cudaGetSymbolAddress((void**)&abig, g_abig);
    cudaGetSymbolAddress((void**)&wbig, g_wbig);

    static bool attr_set = false;
    if (!attr_set) {
        cudaFuncSetAttribute(gemm_hmma, cudaFuncAttributeMaxDynamicSharedMemorySize, GSMEM);
        cudaFuncSetAttribute(flash_kernel, cudaFuncAttributeMaxDynamicSharedMemorySize,
                             (128 * FH + 64 * FH + 64 * FH + 64 * FP) * (int)sizeof(float));
        attr_set = true;
    }

    rope_table_kernel<<<SEQ, 32>>>();

    // Split conversions
    split_bf16_kernel<<<(SEQ * DIM) / 256, 256>>>(x, abig, 1);
    split_bf16_kernel<<<(DIM * DIM) / 256, 256>>>(Wq,   wbig + 0 * (size_t)DIM * KE, 0);
    split_bf16_kernel<<<(DIM * DIM) / 256, 256>>>(Wk,   wbig + 1 * (size_t)DIM * KE, 0);
    split_bf16_kernel<<<(DIM * DIM) / 256, 256>>>(Wv,   wbig + 2 * (size_t)DIM * KE, 0);
    split_bf16_kernel<<<(DIM * DIM) / 256, 256>>>(Wout, wbig + 3 * (size_t)DIM * KE, 0);

    // QKV projections on tensor cores (HMMA)
    dim3 gg(DIM / TN, SEQ / TM);
    gemm_hmma<<<gg, 256, GSMEM>>>(abig, wbig + 0 * (size_t)DIM * KE, q);
    gemm_hmma<<<gg, 256, GSMEM>>>(abig, wbig + 1 * (size_t)DIM * KE, k);
    gemm_hmma<<<gg, 256, GSMEM>>>(abig, wbig + 2 * (size_t)DIM * KE, v);

    postproc_kernel<<<(SEQ * NH) / 8, 256>>>(v1, lam);

    int flash_smem = (128 * FH + 64 * FH + 64 * FH + 64 * FP) * (int)sizeof(float);
    flash_kernel<<<dim3(NH, SEQ / 128), 256, flash_smem>>>();

    // Output projection
    split_bf16_kernel<<<(SEQ * DIM) / 256, 256>>>(att, abig, 1);
    gemm_hmma<<<gg, 256, GSMEM>>>(abig, wbig + 3 * (size_t)DIM * KE, out);

    if (out_size >= 2 * SEQ * DIM) {
        int n4 = (SEQ * DIM) / 4;
        copy_kernel<<<(n4 + 255) / 256, 256>>>((const float4*)v1,
                                               (float4*)(out + SEQ * DIM), n4);
    }
}

// round 7
// speedup vs baseline: 5.2190x; 1.4640x over previous
#include <cuda_runtime.h>
#include <cuda_bf16.h>
#include <math.h>
#include <stdint.h>

// Problem constants
#define SEQ  2048
#define DIM  1024
#define NH   16
#define HD   64
#define KE   3072      // split-bf16 effective K (3 x 1024)

// Scratch (device globals; allocations are forbidden)
__device__ float g_q[SEQ * DIM];
__device__ float g_k[SEQ * DIM];
__device__ float g_v[SEQ * DIM];
__device__ float g_att[SEQ * DIM];
__device__ float g_cos[SEQ * 32];
__device__ float g_sin[SEQ * 32];
__device__ __nv_bfloat16 g_abig[SEQ * KE];        // [Ah|Ah|Al] for x / att
__device__ __nv_bfloat16 g_wbig[4][DIM * KE];     // [Wh|Wl|Wh] per weight

// ===========================================================================
// Arch-generic tensor-core helpers (sm_80+; compile on bare sm_103 target)
// ===========================================================================
__device__ __forceinline__ uint32_t smem_u32(const void* p) {
    uint32_t a;
    asm("{ .reg .u64 t; cvta.to.shared.u64 t, %1; cvt.u32.u64 %0, t; }"
        : "=r"(a) : "l"(p));
    return a;
}
__device__ __forceinline__ void ldsm_x4(uint32_t* r, uint32_t addr) {
    asm volatile("ldmatrix.sync.aligned.m8n8.x4.shared.b16 {%0,%1,%2,%3}, [%4];"
                 : "=r"(r[0]), "=r"(r[1]), "=r"(r[2]), "=r"(r[3]) : "r"(addr));
}
__device__ __forceinline__ void ldsm_x4_t(uint32_t* r, uint32_t addr) {
    asm volatile("ldmatrix.sync.aligned.m8n8.x4.trans.shared.b16 {%0,%1,%2,%3}, [%4];"
                 : "=r"(r[0]), "=r"(r[1]), "=r"(r[2]), "=r"(r[3]) : "r"(addr));
}
__device__ __forceinline__ void mma16816(float* d, const uint32_t* a, const uint32_t* b) {
    asm volatile("mma.sync.aligned.m16n8k16.row.col.f32.bf16.bf16.f32 "
                 "{%0,%1,%2,%3}, {%4,%5,%6,%7}, {%8,%9}, {%0,%1,%2,%3};"
                 : "+f"(d[0]), "+f"(d[1]), "+f"(d[2]), "+f"(d[3])
                 : "r"(a[0]), "r"(a[1]), "r"(a[2]), "r"(a[3]),
                   "r"(b[0]), "r"(b[1]));
}
__device__ __forceinline__ void cp_async16(uint32_t dst, const void* src) {
    asm volatile("cp.async.cg.shared.global [%0], [%1], 16;" :: "r"(dst), "l"(src));
}
#define CP_COMMIT() asm volatile("cp.async.commit_group;" ::: "memory")
#define CP_WAIT(n)  asm volatile("cp.async.wait_group %0;" :: "n"(n) : "memory")

__device__ __forceinline__ uint32_t sw128(uint32_t off) {
    return off ^ ((off >> 3) & 0x70);
}
// pack (x,y) into bf16x2 hi; residual into *lo
__device__ __forceinline__ uint32_t pack_split(float x, float y, uint32_t* lo) {
    __nv_bfloat16 hx = __float2bfloat16(x), hy = __float2bfloat16(y);
    float rx = x - __bfloat162float(hx), ry = y - __bfloat162float(hy);
    __nv_bfloat162 hh = __halves2bfloat162(hx, hy);
    __nv_bfloat162 ll = __floats2bfloat162_rn(rx, ry);
    *lo = *(uint32_t*)&ll;
    return *(uint32_t*)&hh;
}

// ===========================================================================
// RoPE table
// ===========================================================================
__global__ void rope_table_kernel() {
    int t = blockIdx.x;
    int i = threadIdx.x;
    double p = pow(10000.0, (double)i / 32.0);
    float invf = 1.0f / (float)p;
    float f = (float)t * invf;
    double fd = (double)f;
    g_cos[t * 32 + i] = (float)cos(fd);
    g_sin[t * 32 + i] = (float)sin(fd);
}

// ===========================================================================
// Splits: fp32 -> bf16 triples.
// Activations: row = [H | H | L].  Weights: row = [W H | L | H], 4 fused.
// ===========================================================================
__global__ __launch_bounds__(256) void split_act_kernel(const float* __restrict__ src,
                                                        __nv_bfloat16* __restrict__ dst) {
    int idx = blockIdx.x * 256 + threadIdx.x;
    int r = idx >> 10, c = idx & 1023;
    float x = src[idx];
    __nv_bfloat16 h = __float2bfloat16(x);
    __nv_bfloat16 l = __float2bfloat16(x - __bfloat162float(h));
    size_t b = (size_t)r * KE + c;
    dst[b] = h; dst[b + 1024] = h; dst[b + 2048] = l;
}

__global__ __launch_bounds__(256) void split_w4_kernel(const float* __restrict__ Wq,
                                                       const float* __restrict__ Wk,
                                                       const float* __restrict__ Wv,
                                                       const float* __restrict__ Wo,
                                                       __nv_bfloat16* __restrict__ dst) {
    int wsel = blockIdx.y;
    const float* src = (wsel == 0) ? Wq : (wsel == 1) ? Wk : (wsel == 2) ? Wv : Wo;
    __nv_bfloat16* d = dst + (size_t)wsel * DIM * KE;
    int idx = blockIdx.x * 256 + threadIdx.x;
    int r = idx >> 10, c = idx & 1023;
    float x = src[idx];
    __nv_bfloat16 h = __float2bfloat16(x);
    __nv_bfloat16 l = __float2bfloat16(x - __bfloat162float(h));
    size_t b = (size_t)r * KE + c;
    d[b] = h; d[b + 1024] = l; d[b + 2048] = h;
}

// ===========================================================================
// HMMA NT GEMM: C[2048,1024] fp32 = A'[2048,KE] @ B'[1024,KE]^T  (R6, proven)
// ===========================================================================
#define TM 128
#define TN 128
#define KC 64
#define NCH (KE / KC)              // 48
#define ASZ (TM * 128)
#define BSZ (TN * 128)
#define GSMEM (2 * (ASZ + BSZ))    // 64 KB

__device__ __forceinline__ void g_load_chunk(uint32_t sb, int buf,
                                             const char* Ag, const char* Bg,
                                             int c, int tid) {
    uint32_t ab = sb + buf * (ASZ + BSZ);
    uint32_t bb = ab + ASZ;
    size_t coff = (size_t)c * 128;
#pragma unroll
    for (int i = 0; i < 4; i++) {
        int u = tid + i * 256;
        int row = u >> 3, seg = u & 7;
        uint32_t off = row * 128 + seg * 16;
        cp_async16(ab + sw128(off), Ag + (size_t)row * (KE * 2) + coff + seg * 16);
    }
#pragma unroll
    for (int i = 0; i < 4; i++) {
        int u = tid + i * 256;
        int row = u >> 3, seg = u & 7;
        uint32_t off = row * 128 + seg * 16;
        cp_async16(bb + sw128(off), Bg + (size_t)row * (KE * 2) + coff + seg * 16);
    }
}

__global__ __launch_bounds__(256) void gemm_hmma(const __nv_bfloat16* __restrict__ A,
                                                 const __nv_bfloat16* __restrict__ B,
                                                 float* __restrict__ C) {
    extern __shared__ __align__(128) char smem[];
    uint32_t sb = smem_u32(smem);
    int tid = threadIdx.x;
    int wid = tid >> 5, lane = tid & 31;
    int wm = wid & 1, wn = wid >> 1;
    int bm = blockIdx.y * TM, bn = blockIdx.x * TN;

    const char* Ag = (const char*)(A + (size_t)bm * KE);
    const char* Bg = (const char*)(B + (size_t)bn * KE);

    float acc[4][4][4];
#pragma unroll
    for (int mt = 0; mt < 4; mt++)
#pragma unroll
        for (int nt = 0; nt < 4; nt++)
#pragma unroll
            for (int r = 0; r < 4; r++) acc[mt][nt][r] = 0.f;

    g_load_chunk(sb, 0, Ag, Bg, 0, tid);
    CP_COMMIT();

    int a_row = wm * 64 + (lane & 15);
    int a_kb  = (lane >> 4) * 16;
    int b_row = wn * 32 + (lane & 7) + ((lane >> 4) << 3);
    int b_kb  = ((lane >> 3) & 1) * 16;

    for (int c = 0; c < NCH; c++) {
        int buf = c & 1;
        if (c + 1 < NCH) {
            g_load_chunk(sb, buf ^ 1, Ag, Bg, c + 1, tid);
            CP_COMMIT();
            CP_WAIT(1);
        } else {
            CP_WAIT(0);
        }
        __syncthreads();

        uint32_t abase = sb + buf * (ASZ + BSZ);
        uint32_t bbase = abase + ASZ;
#pragma unroll
        for (int ks = 0; ks < 4; ks++) {
            uint32_t af[4][4];
#pragma unroll
            for (int mt = 0; mt < 4; mt++) {
                uint32_t off = (a_row + mt * 16) * 128 + ks * 32 + a_kb;
                ldsm_x4(af[mt], abase + sw128(off));
            }
            uint32_t bf[2][4];
#pragma unroll
            for (int bt = 0; bt < 2; bt++) {
                uint32_t off = (b_row + bt * 16) * 128 + ks * 32 + b_kb;
                ldsm_x4(bf[bt], bbase + sw128(off));
            }
#pragma unroll
            for (int mt = 0; mt < 4; mt++)
#pragma unroll
                for (int nt = 0; nt < 4; nt++)
                    mma16816(acc[mt][nt], af[mt], &bf[nt >> 1][(nt & 1) * 2]);
        }
        __syncthreads();
    }

    int g = lane >> 2, cp = (lane & 3) * 2;
#pragma unroll
    for (int mt = 0; mt < 4; mt++) {
#pragma unroll
        for (int nt = 0; nt < 4; nt++) {
            int row = bm + wm * 64 + mt * 16 + g;
            int col = bn + wn * 32 + nt * 8 + cp;
            float2 v0 = make_float2(acc[mt][nt][0], acc[mt][nt][1]);
            float2 v1 = make_float2(acc[mt][nt][2], acc[mt][nt][3]);
            *(float2*)&C[(size_t)row * DIM + col] = v0;
            *(float2*)&C[(size_t)(row + 8) * DIM + col] = v1;
        }
    }
}

// ===========================================================================
// Post-process: V blend, rmsnorm+rope on Q/K.
// ===========================================================================
__global__ __launch_bounds__(256) void postproc_kernel(const float* __restrict__ v1,
                                                       const float* __restrict__ lam_p) {
    int warp = threadIdx.x >> 5, lane = threadIdx.x & 31;
    int row = blockIdx.x * 8 + warp;
    int s_idx = row >> 4;
    int h = row & 15;
    int base = s_idx * DIM + h * HD;
    float lam = *lam_p;

    {
        float a = g_v[base + lane], b = g_v[base + lane + 32];
        g_v[base + lane]      = (1.f - lam) * a + lam * v1[base + lane];
        g_v[base + lane + 32] = (1.f - lam) * b + lam * v1[base + lane + 32];
    }
    float c = g_cos[s_idx * 32 + lane];
    float sn = g_sin[s_idx * 32 + lane];
    const float eps = 1.1920928955078125e-07f;
    {
        float a = g_q[base + lane], b = g_q[base + lane + 32];
        float ss = a * a + b * b;
#pragma unroll
        for (int off = 16; off; off >>= 1) ss += __shfl_xor_sync(0xffffffffu, ss, off);
        float mean = ss * (1.f / 64.f) + eps;
        float r = rsqrtf(mean);
        r = r * (1.5f - 0.5f * mean * r * r);
        a *= r; b *= r;
        g_q[base + lane]      = a * c + b * sn;
        g_q[base + lane + 32] = -a * sn + b * c;
    }
    {
        float a = g_k[base + lane], b = g_k[base + lane + 32];
        float ss = a * a + b * b;
#pragma unroll
        for (int off = 16; off; off >>= 1) ss += __shfl_xor_sync(0xffffffffu, ss, off);
        float mean = ss * (1.f / 64.f) + eps;
        float r = rsqrtf(mean);
        r = r * (1.5f - 0.5f * mean * r * r);
        a *= r; b *= r;
        g_k[base + lane]      = a * c + b * sn;
        g_k[base + lane + 32] = -a * sn + b * c;
    }
}

// ===========================================================================
// Flash attention v3: HMMA bf16 with 3-term split precision.
// Block = (128 q rows, head), 8 warps; warp owns 16 q rows.
// QK = qh.kh + qh.kl + ql.kh ; PV = Ph.Vh + Ph.Vl + Pl.Vh
// K/V panels: [kv 64][d 64] bf16, 128B rows, sw128. V B-frags via ldmatrix.trans.
// ===========================================================================
#define FOKH 0
#define FOKL 8192
#define FOVH 16384
#define FOVL 24576
#define FSMEM 32768

__global__ __launch_bounds__(256, 1) void flash_hmma() {
    extern __shared__ __align__(128) char fsm[];
    uint32_t sb = smem_u32(fsm);

    int h  = blockIdx.x;
    int qt = 15 - (int)blockIdx.y;          // LPT: heavy tiles first
    int q0 = qt * 128;
    int tid = threadIdx.x, w = tid >> 5, lane = tid & 31;
    int g = lane >> 2, t4 = lane & 3;

    // --- Q fragments in registers: scale by 0.125 then split hi/lo ---
    uint32_t aqh[4][4], aql[4][4];
    {
        int row0 = q0 + w * 16 + g;
#pragma unroll
        for (int ks = 0; ks < 4; ks++) {
            int cb = h * HD + ks * 16 + 2 * t4;
            float2 f[4];
            f[0] = *(const float2*)&g_q[(size_t)row0 * DIM + cb];
            f[1] = *(const float2*)&g_q[(size_t)(row0 + 8) * DIM + cb];
            f[2] = *(const float2*)&g_q[(size_t)row0 * DIM + cb + 8];
            f[3] = *(const float2*)&g_q[(size_t)(row0 + 8) * DIM + cb + 8];
#pragma unroll
            for (int r = 0; r < 4; r++)
                aqh[ks][r] = pack_split(f[r].x * 0.125f, f[r].y * 0.125f, &aql[ks][r]);
        }
    }

    float m0 = -1e30f, m1 = -1e30f, l0 = 0.f, l1 = 0.f;
    float o[8][4];
#pragma unroll
    for (int nt = 0; nt < 8; nt++)
#pragma unroll
        for (int r = 0; r < 4; r++) o[nt][r] = 0.f;

    // ldmatrix lane constants
    int nbr = (lane & 7) + ((lane >> 4) << 3);      // non-trans (K) row add
    int nbk = ((lane >> 3) & 1) * 16;               // non-trans k-byte add
    int tvr = (lane & 7) + 8 * ((lane >> 3) & 1);   // trans (V) row add
    int tvc = 16 * (lane >> 4);                     // trans col-byte add

    int nkt = 2 * qt + 2;
    for (int kt = 0; kt < nkt; kt++) {
        __syncthreads();    // panel reads from previous iter done
        // --- load K,V tile; split into bf16 hi/lo panels ---
        {
            int r = tid >> 2, d0 = (tid & 3) * 16;
            size_t gb = (size_t)(kt * 64 + r) * DIM + h * HD;
#pragma unroll
            for (int j = 0; j < 4; j++) {
                int d = d0 + 4 * j;
                float4 kf = *(const float4*)&g_k[gb + d];
                float4 vf = *(const float4*)&g_v[gb + d];
                uint32_t off = sw128((uint32_t)(r * 128 + d * 2));
                uint32_t lo;
                uint32_t hi01 = pack_split(kf.x, kf.y, &lo);
                *(uint32_t*)(fsm + FOKH + off) = hi01;
                *(uint32_t*)(fsm + FOKL + off) = lo;
                uint32_t hi23 = pack_split(kf.z, kf.w, &lo);
                *(uint32_t*)(fsm + FOKH + off + 4) = hi23;
                *(uint32_t*)(fsm + FOKL + off + 4) = lo;
                hi01 = pack_split(vf.x, vf.y, &lo);
                *(uint32_t*)(fsm + FOVH + off) = hi01;
                *(uint32_t*)(fsm + FOVL + off) = lo;
                hi23 = pack_split(vf.z, vf.w, &lo);
                *(uint32_t*)(fsm + FOVH + off + 4) = hi23;
                *(uint32_t*)(fsm + FOVL + off + 4) = lo;
            }
        }
        __syncthreads();

        if (kt * 64 > q0 + w * 16 + 15) continue;   // warp fully masked: skip compute

        // --- QK: 3 split terms ---
        float s[8][4];
#pragma unroll
        for (int nt = 0; nt < 8; nt++)
#pragma unroll
            for (int r = 0; r < 4; r++) s[nt][r] = 0.f;

#pragma unroll
        for (int t = 0; t < 3; t++) {
            uint32_t (*aq)[4] = (t == 2) ? aql : aqh;
            uint32_t kp = sb + ((t == 1) ? FOKL : FOKH);
#pragma unroll
            for (int ks = 0; ks < 4; ks++) {
                uint32_t bfr[4][4];
#pragma unroll
                for (int bt = 0; bt < 4; bt++) {
                    uint32_t off = sw128((uint32_t)((nbr + bt * 16) * 128 + ks * 32 + nbk));
                    ldsm_x4(bfr[bt], kp + off);
                }
#pragma unroll
                for (int nt = 0; nt < 8; nt++)
                    mma16816(s[nt], aq[ks], &bfr[nt >> 1][(nt & 1) * 2]);
            }
        }

        // --- causal mask (diagonal region only) ---
        if (kt >= 2 * qt) {
            int r0 = q0 + w * 16 + g, r1 = r0 + 8;
            int c0 = kt * 64 + 2 * t4;
#pragma unroll
            for (int nt = 0; nt < 8; nt++) {
                int c = c0 + nt * 8;
                if (c     > r0) s[nt][0] = -1e30f;
                if (c + 1 > r0) s[nt][1] = -1e30f;
                if (c     > r1) s[nt][2] = -1e30f;
                if (c + 1 > r1) s[nt][3] = -1e30f;
            }
        }

        // --- online softmax (rows g and g+8) ---
        float mx0 = -1e30f, mx1 = -1e30f;
#pragma unroll
        for (int nt = 0; nt < 8; nt++) {
            mx0 = fmaxf(mx0, fmaxf(s[nt][0], s[nt][1]));
            mx1 = fmaxf(mx1, fmaxf(s[nt][2], s[nt][3]));
        }
        mx0 = fmaxf(mx0, __shfl_xor_sync(0xffffffffu, mx0, 1));
        mx0 = fmaxf(mx0, __shfl_xor_sync(0xffffffffu, mx0, 2));
        mx1 = fmaxf(mx1, __shfl_xor_sync(0xffffffffu, mx1, 1));
        mx1 = fmaxf(mx1, __shfl_xor_sync(0xffffffffu, mx1, 2));
        float mn0 = fmaxf(m0, mx0), mn1 = fmaxf(m1, mx1);
        float al0 = __expf(m0 - mn0), al1 = __expf(m1 - mn1);
        float sum0 = 0.f, sum1 = 0.f;
#pragma unroll
        for (int nt = 0; nt < 8; nt++) {
            s[nt][0] = __expf(s[nt][0] - mn0);
            s[nt][1] = __expf(s[nt][1] - mn0);
            s[nt][2] = __expf(s[nt][2] - mn1);
            s[nt][3] = __expf(s[nt][3] - mn1);
            sum0 += s[nt][0] + s[nt][1];
            sum1 += s[nt][2] + s[nt][3];
        }
        sum0 += __shfl_xor_sync(0xffffffffu, sum0, 1);
        sum0 += __shfl_xor_sync(0xffffffffu, sum0, 2);
        sum1 += __shfl_xor_sync(0xffffffffu, sum1, 1);
        sum1 += __shfl_xor_sync(0xffffffffu, sum1, 2);
        l0 = l0 * al0 + sum0;  m0 = mn0;
        l1 = l1 * al1 + sum1;  m1 = mn1;
#pragma unroll
        for (int nt = 0; nt < 8; nt++) {
            o[nt][0] *= al0; o[nt][1] *= al0;
            o[nt][2] *= al1; o[nt][3] *= al1;
        }

        // --- pack P into A-fragments (hi + residual lo) ---
        uint32_t ph[4][4], pl[4][4];
#pragma unroll
        for (int j = 0; j < 4; j++) {
            int t0 = 2 * j, t1 = 2 * j + 1;
            ph[j][0] = pack_split(s[t0][0], s[t0][1], &pl[j][0]);
            ph[j][1] = pack_split(s[t0][2], s[t0][3], &pl[j][1]);
            ph[j][2] = pack_split(s[t1][0], s[t1][1], &pl[j][2]);
            ph[j][3] = pack_split(s[t1][2], s[t1][3], &pl[j][3]);
        }

        // --- PV: 3 split terms; V B-frags via ldmatrix.trans ---
#pragma unroll
        for (int c = 0; c < 3; c++) {
            uint32_t (*ap)[4] = (c == 2) ? pl : ph;
            uint32_t vp = sb + ((c == 1) ? FOVL : FOVH);
#pragma unroll
            for (int j = 0; j < 4; j++) {
                uint32_t bv[4][4];
#pragma unroll
                for (int bt = 0; bt < 4; bt++) {
                    uint32_t off = sw128((uint32_t)((j * 16 + tvr) * 128 + bt * 32 + tvc));
                    ldsm_x4_t(bv[bt], vp + off);
                }
#pragma unroll
                for (int nt = 0; nt < 8; nt++)
                    mma16816(o[nt], ap[j], &bv[nt >> 1][(nt & 1) * 2]);
            }
        }
    }

    // --- normalize + write ---
    float i0 = 1.f / l0, i1 = 1.f / l1;
    int row0 = q0 + w * 16 + g;
#pragma unroll
    for (int nt = 0; nt < 8; nt++) {
        int col = h * HD + nt * 8 + 2 * t4;
        *(float2*)&g_att[(size_t)row0 * DIM + col] =
            make_float2(o[nt][0] * i0, o[nt][1] * i0);
        *(float2*)&g_att[(size_t)(row0 + 8) * DIM + col] =
            make_float2(o[nt][2] * i1, o[nt][3] * i1);
    }
}

// v1 passthrough copy
__global__ void copy_kernel(const float4* __restrict__ src, float4* __restrict__ dst, int n4) {
    int i = blockIdx.x * blockDim.x + threadIdx.x;
    if (i < n4) dst[i] = src[i];
}

// ===========================================================================
extern "C" void kernel_launch(void* const* d_in, const int* in_sizes, int n_in,
                              void* d_out, int out_size) {
    const float* x    = (const float*)d_in[0];
    const float* v1   = (const float*)d_in[1];
    const float* Wq   = (const float*)d_in[2];
    const float* Wk   = (const float*)d_in[3];
    const float* Wv   = (const float*)d_in[4];
    const float* Wout = (const float*)d_in[5];
    const float* lam  = (const float*)d_in[6];
    float* out = (float*)d_out;

    float *q, *k, *v, *att;
    __nv_bfloat16 *abig, *wbig;
    cudaGetSymbolAddress((void**)&q, g_q);
    cudaGetSymbolAddress((void**)&k, g_k);
    cudaGetSymbolAddress((void**)&v, g_v);
    cudaGetSymbolAddress((void**)&att, g_att);
    cudaGetSymbolAddress((void**)&abig, g_abig);
    cudaGetSymbolAddress((void**)&wbig, g_wbig);

    static bool attr_set = false;
    if (!attr_set) {
        cudaFuncSetAttribute(gemm_hmma, cudaFuncAttributeMaxDynamicSharedMemorySize, GSMEM);
        attr_set = true;
    }

    rope_table_kernel<<<SEQ, 32>>>();

    // Split conversions
    split_act_kernel<<<(SEQ * DIM) / 256, 256>>>(x, abig);
    split_w4_kernel<<<dim3((DIM * DIM) / 256, 4), 256>>>(Wq, Wk, Wv, Wout, wbig);

    // QKV projections (HMMA)
    dim3 gg(DIM / TN, SEQ / TM);
    gemm_hmma<<<gg, 256, GSMEM>>>(abig, wbig + 0 * (size_t)DIM * KE, q);
    gemm_hmma<<<gg, 256, GSMEM>>>(abig, wbig + 1 * (size_t)DIM * KE, k);
    gemm_hmma<<<gg, 256, GSMEM>>>(abig, wbig + 2 * (size_t)DIM * KE, v);

    postproc_kernel<<<(SEQ * NH) / 8, 256>>>(v1, lam);

    // Flash attention (HMMA, split precision)
    flash_hmma<<<dim3(NH, SEQ / 128), 256, FSMEM>>>();

    // Output projection
    split_act_kernel<<<(SEQ * DIM) / 256, 256>>>(att, abig);
    gemm_hmma<<<gg, 256, GSMEM>>>(abig, wbig + 3 * (size_t)DIM * KE, out);

    if (out_size >= 2 * SEQ * DIM) {
        int n4 = (SEQ * DIM) / 4;
        copy_kernel<<<(n4 + 255) / 256, 256>>>((const float4*)v1,
                                               (float4*)(out + SEQ * DIM), n4);
    }
}

// round 8
// speedup vs baseline: 6.0279x; 1.1550x over previous
#include <cuda_runtime.h>
#include <cuda_bf16.h>
#include <math.h>
#include <stdint.h>

// Problem constants
#define SEQ  2048
#define DIM  1024
#define NH   16
#define HD   64
#define KE   3072      // split-bf16 effective K (3 x 1024)

// Scratch (device globals; allocations are forbidden)
__device__ float g_q[SEQ * DIM];
__device__ float g_k[SEQ * DIM];
__device__ float g_v[SEQ * DIM];
__device__ float g_cos[SEQ * 32];
__device__ float g_sin[SEQ * 32];
__device__ __nv_bfloat16 g_kh[SEQ * DIM], g_kl[SEQ * DIM];
__device__ __nv_bfloat16 g_vh[SEQ * DIM], g_vl[SEQ * DIM];
__device__ __nv_bfloat16 g_abig[SEQ * KE];        // [Ah|Ah|Al] for x / att
__device__ __nv_bfloat16 g_wbig[4][DIM * KE];     // [Wh|Wl|Wh] per weight

// ===========================================================================
// Helpers (sm_80+ generic)
// ===========================================================================
__device__ __forceinline__ uint32_t smem_u32(const void* p) {
    uint32_t a;
    asm("{ .reg .u64 t; cvta.to.shared.u64 t, %1; cvt.u32.u64 %0, t; }"
        : "=r"(a) : "l"(p));
    return a;
}
__device__ __forceinline__ void ldsm_x4(uint32_t* r, uint32_t addr) {
    asm volatile("ldmatrix.sync.aligned.m8n8.x4.shared.b16 {%0,%1,%2,%3}, [%4];"
                 : "=r"(r[0]), "=r"(r[1]), "=r"(r[2]), "=r"(r[3]) : "r"(addr));
}
__device__ __forceinline__ void ldsm_x4_t(uint32_t* r, uint32_t addr) {
    asm volatile("ldmatrix.sync.aligned.m8n8.x4.trans.shared.b16 {%0,%1,%2,%3}, [%4];"
                 : "=r"(r[0]), "=r"(r[1]), "=r"(r[2]), "=r"(r[3]) : "r"(addr));
}
__device__ __forceinline__ void mma16816(float* d, const uint32_t* a, const uint32_t* b) {
    asm volatile("mma.sync.aligned.m16n8k16.row.col.f32.bf16.bf16.f32 "
                 "{%0,%1,%2,%3}, {%4,%5,%6,%7}, {%8,%9}, {%0,%1,%2,%3};"
                 : "+f"(d[0]), "+f"(d[1]), "+f"(d[2]), "+f"(d[3])
                 : "r"(a[0]), "r"(a[1]), "r"(a[2]), "r"(a[3]),
                   "r"(b[0]), "r"(b[1]));
}
__device__ __forceinline__ void cp_async16(uint32_t dst, const void* src) {
    asm volatile("cp.async.cg.shared.global [%0], [%1], 16;" :: "r"(dst), "l"(src));
}
#define CP_COMMIT() asm volatile("cp.async.commit_group;" ::: "memory")
#define CP_WAIT(n)  asm volatile("cp.async.wait_group %0;" :: "n"(n) : "memory")

__device__ __forceinline__ uint32_t sw128(uint32_t off) {
    return off ^ ((off >> 3) & 0x70);
}
__device__ __forceinline__ uint32_t pack_split(float x, float y, uint32_t* lo) {
    __nv_bfloat16 hx = __float2bfloat16(x), hy = __float2bfloat16(y);
    float rx = x - __bfloat162float(hx), ry = y - __bfloat162float(hy);
    __nv_bfloat162 hh = __halves2bfloat162(hx, hy);
    __nv_bfloat162 ll = __floats2bfloat162_rn(rx, ry);
    *lo = *(uint32_t*)&ll;
    return *(uint32_t*)&hh;
}

// ===========================================================================
// RoPE table
// ===========================================================================
__global__ void rope_table_kernel() {
    int t = blockIdx.x;
    int i = threadIdx.x;
    double p = pow(10000.0, (double)i / 32.0);
    float invf = 1.0f / (float)p;
    float f = (float)t * invf;
    double fd = (double)f;
    g_cos[t * 32 + i] = (float)cos(fd);
    g_sin[t * 32 + i] = (float)sin(fd);
}

// ===========================================================================
// Splits: fp32 -> bf16 triples.
// ===========================================================================
__global__ __launch_bounds__(256) void split_act_kernel(const float* __restrict__ src,
                                                        __nv_bfloat16* __restrict__ dst) {
    int idx = blockIdx.x * 256 + threadIdx.x;
    int r = idx >> 10, c = idx & 1023;
    float x = src[idx];
    __nv_bfloat16 h = __float2bfloat16(x);
    __nv_bfloat16 l = __float2bfloat16(x - __bfloat162float(h));
    size_t b = (size_t)r * KE + c;
    dst[b] = h; dst[b + 1024] = h; dst[b + 2048] = l;
}

__global__ __launch_bounds__(256) void split_w4_kernel(const float* __restrict__ Wq,
                                                       const float* __restrict__ Wk,
                                                       const float* __restrict__ Wv,
                                                       const float* __restrict__ Wo,
                                                       __nv_bfloat16* __restrict__ dst) {
    int wsel = blockIdx.y;
    const float* src = (wsel == 0) ? Wq : (wsel == 1) ? Wk : (wsel == 2) ? Wv : Wo;
    __nv_bfloat16* d = dst + (size_t)wsel * DIM * KE;
    int idx = blockIdx.x * 256 + threadIdx.x;
    int r = idx >> 10, c = idx & 1023;
    float x = src[idx];
    __nv_bfloat16 h = __float2bfloat16(x);
    __nv_bfloat16 l = __float2bfloat16(x - __bfloat162float(h));
    size_t b = (size_t)r * KE + c;
    d[b] = h; d[b + 1024] = l; d[b + 2048] = h;
}

// ===========================================================================
// HMMA NT GEMM, 3-stage cp.async pipeline, fused over blockIdx.z outputs.
// C[z][2048,1024] fp32 = A'[2048,KE] @ B'[z][1024,KE]^T
// ===========================================================================
#define TM 128
#define TN 128
#define NCH (KE / 64)              // 48
#define ASZ (TM * 128)
#define BSZ (TN * 128)
#define SSTG (ASZ + BSZ)           // 32 KB per stage
#define GSMEM (3 * SSTG)           // 96 KB

__device__ __forceinline__ void g_load_chunk(uint32_t sb, int st,
                                             const char* Ag, const char* Bg,
                                             int c, int tid) {
    uint32_t ab = sb + st * SSTG;
    uint32_t bb = ab + ASZ;
    size_t coff = (size_t)c * 128;
#pragma unroll
    for (int i = 0; i < 4; i++) {
        int u = tid + i * 256;
        int row = u >> 3, seg = u & 7;
        uint32_t off = row * 128 + seg * 16;
        cp_async16(ab + sw128(off), Ag + (size_t)row * (KE * 2) + coff + seg * 16);
    }
#pragma unroll
    for (int i = 0; i < 4; i++) {
        int u = tid + i * 256;
        int row = u >> 3, seg = u & 7;
        uint32_t off = row * 128 + seg * 16;
        cp_async16(bb + sw128(off), Bg + (size_t)row * (KE * 2) + coff + seg * 16);
    }
}

__global__ __launch_bounds__(256, 2) void gemm_hmma3(const __nv_bfloat16* __restrict__ A,
                                                     const __nv_bfloat16* __restrict__ Bbase,
                                                     float* __restrict__ C0,
                                                     float* __restrict__ C1,
                                                     float* __restrict__ C2) {
    extern __shared__ __align__(128) char smem[];
    uint32_t sb = smem_u32(smem);
    int z = blockIdx.z;
    const __nv_bfloat16* B = Bbase + (size_t)z * DIM * KE;
    float* C = (z == 0) ? C0 : (z == 1) ? C1 : C2;

    int tid = threadIdx.x;
    int wid = tid >> 5, lane = tid & 31;
    int wm = wid & 1, wn = wid >> 1;
    int bm = blockIdx.y * TM, bn = blockIdx.x * TN;

    const char* Ag = (const char*)(A + (size_t)bm * KE);
    const char* Bg = (const char*)(B + (size_t)bn * KE);

    float acc[4][4][4];
#pragma unroll
    for (int mt = 0; mt < 4; mt++)
#pragma unroll
        for (int nt = 0; nt < 4; nt++)
#pragma unroll
            for (int r = 0; r < 4; r++) acc[mt][nt][r] = 0.f;

    g_load_chunk(sb, 0, Ag, Bg, 0, tid);
    CP_COMMIT();
    g_load_chunk(sb, 1, Ag, Bg, 1, tid);
    CP_COMMIT();

    int a_row = wm * 64 + (lane & 15);
    int a_kb  = (lane >> 4) * 16;
    int b_row = wn * 32 + (lane & 7) + ((lane >> 4) << 3);
    int b_kb  = ((lane >> 3) & 1) * 16;

    int st = 0;        // stage holding chunk c
    for (int c = 0; c < NCH; c++) {
        if (c + 2 < NCH) {
            int ns = st + 2; if (ns >= 3) ns -= 3;
            g_load_chunk(sb, ns, Ag, Bg, c + 2, tid);
            CP_COMMIT();
            CP_WAIT(2);
        } else if (c + 1 < NCH) {
            CP_WAIT(1);
        } else {
            CP_WAIT(0);
        }
        __syncthreads();

        uint32_t abase = sb + st * SSTG;
        uint32_t bbase = abase + ASZ;
#pragma unroll
        for (int ks = 0; ks < 4; ks++) {
            uint32_t af[4][4];
#pragma unroll
            for (int mt = 0; mt < 4; mt++) {
                uint32_t off = (a_row + mt * 16) * 128 + ks * 32 + a_kb;
                ldsm_x4(af[mt], abase + sw128(off));
            }
            uint32_t bf[2][4];
#pragma unroll
            for (int bt = 0; bt < 2; bt++) {
                uint32_t off = (b_row + bt * 16) * 128 + ks * 32 + b_kb;
                ldsm_x4(bf[bt], bbase + sw128(off));
            }
#pragma unroll
            for (int mt = 0; mt < 4; mt++)
#pragma unroll
                for (int nt = 0; nt < 4; nt++)
                    mma16816(acc[mt][nt], af[mt], &bf[nt >> 1][(nt & 1) * 2]);
        }
        __syncthreads();
        if (++st == 3) st = 0;
    }

    int g = lane >> 2, cp = (lane & 3) * 2;
#pragma unroll
    for (int mt = 0; mt < 4; mt++) {
#pragma unroll
        for (int nt = 0; nt < 4; nt++) {
            int row = bm + wm * 64 + mt * 16 + g;
            int col = bn + wn * 32 + nt * 8 + cp;
            float2 v0 = make_float2(acc[mt][nt][0], acc[mt][nt][1]);
            float2 v1 = make_float2(acc[mt][nt][2], acc[mt][nt][3]);
            *(float2*)&C[(size_t)row * DIM + col] = v0;
            *(float2*)&C[(size_t)(row + 8) * DIM + col] = v1;
        }
    }
}

// ===========================================================================
// Post-process: V blend -> split bf16; K rmsnorm+rope -> split bf16;
// Q rmsnorm+rope stays fp32 in g_q.
// ===========================================================================
__global__ __launch_bounds__(256) void postproc_kernel(const float* __restrict__ v1,
                                                       const float* __restrict__ lam_p) {
    int warp = threadIdx.x >> 5, lane = threadIdx.x & 31;
    int row = blockIdx.x * 8 + warp;
    int s_idx = row >> 4;
    int h = row & 15;
    int base = s_idx * DIM + h * HD;
    float lam = *lam_p;

    {
        float a = (1.f - lam) * g_v[base + lane] + lam * v1[base + lane];
        float b = (1.f - lam) * g_v[base + lane + 32] + lam * v1[base + lane + 32];
        __nv_bfloat16 ah = __float2bfloat16(a), bh = __float2bfloat16(b);
        g_vh[base + lane] = ah;
        g_vl[base + lane] = __float2bfloat16(a - __bfloat162float(ah));
        g_vh[base + lane + 32] = bh;
        g_vl[base + lane + 32] = __float2bfloat16(b - __bfloat162float(bh));
    }
    float c = g_cos[s_idx * 32 + lane];
    float sn = g_sin[s_idx * 32 + lane];
    const float eps = 1.1920928955078125e-07f;
    {
        float a = g_q[base + lane], b = g_q[base + lane + 32];
        float ss = a * a + b * b;
#pragma unroll
        for (int off = 16; off; off >>= 1) ss += __shfl_xor_sync(0xffffffffu, ss, off);
        float mean = ss * (1.f / 64.f) + eps;
        float r = rsqrtf(mean);
        r = r * (1.5f - 0.5f * mean * r * r);
        a *= r; b *= r;
        g_q[base + lane]      = a * c + b * sn;
        g_q[base + lane + 32] = -a * sn + b * c;
    }
    {
        float a = g_k[base + lane], b = g_k[base + lane + 32];
        float ss = a * a + b * b;
#pragma unroll
        for (int off = 16; off; off >>= 1) ss += __shfl_xor_sync(0xffffffffu, ss, off);
        float mean = ss * (1.f / 64.f) + eps;
        float r = rsqrtf(mean);
        r = r * (1.5f - 0.5f * mean * r * r);
        a *= r; b *= r;
        float ka = a * c + b * sn;
        float kb = -a * sn + b * c;
        __nv_bfloat16 ah = __float2bfloat16(ka), bh = __float2bfloat16(kb);
        g_kh[base + lane] = ah;
        g_kl[base + lane] = __float2bfloat16(ka - __bfloat162float(ah));
        g_kh[base + lane + 32] = bh;
        g_kl[base + lane + 32] = __float2bfloat16(kb - __bfloat162float(bh));
    }
}

// ===========================================================================
// Flash attention v4: HMMA split-precision, double-buffered cp.async panels
// from precomputed bf16 K/V. Epilogue writes the [H|H|L] split directly.
// ===========================================================================
#define FSTG 32768          // 4 panels x 8 KB per stage
#define FSMEM (2 * FSTG)

__device__ __forceinline__ void f_load_kv(char* fsm, uint32_t sb, int s, int kt,
                                          int h, int tid,
                                          const __nv_bfloat16* kh, const __nv_bfloat16* kl,
                                          const __nv_bfloat16* vh, const __nv_bfloat16* vl) {
    const __nv_bfloat16* srcs[4] = {kh, kl, vh, vl};
#pragma unroll
    for (int p = 0; p < 4; p++) {
        uint32_t pb = sb + s * FSTG + p * 8192;
        const char* gp = (const char*)(srcs[p] + (size_t)(kt * 64) * DIM + h * HD);
#pragma unroll
        for (int i = 0; i < 2; i++) {
            int u = tid + i * 256;
            int r = u >> 3, seg = u & 7;
            uint32_t off = r * 128 + seg * 16;
            cp_async16(pb + sw128(off), gp + (size_t)r * (DIM * 2) + seg * 16);
        }
    }
}

__global__ __launch_bounds__(256, 1) void flash_hmma(__nv_bfloat16* __restrict__ abig) {
    extern __shared__ __align__(128) char fsm[];
    uint32_t sb = smem_u32(fsm);

    int h  = blockIdx.x;
    int qt = 15 - (int)blockIdx.y;          // LPT: heavy tiles first
    int q0 = qt * 128;
    int tid = threadIdx.x, w = tid >> 5, lane = tid & 31;
    int g = lane >> 2, t4 = lane & 3;

    __nv_bfloat16 *kh, *kl, *vh, *vl;
    // device globals are directly addressable in device code
    kh = g_kh; kl = g_kl; vh = g_vh; vl = g_vl;

    // Q fragments: scale by 0.125, split hi/lo
    uint32_t aqh[4][4], aql[4][4];
    {
        int row0 = q0 + w * 16 + g;
#pragma unroll
        for (int ks = 0; ks < 4; ks++) {
            int cb = h * HD + ks * 16 + 2 * t4;
            float2 f[4];
            f[0] = *(const float2*)&g_q[(size_t)row0 * DIM + cb];
            f[1] = *(const float2*)&g_q[(size_t)(row0 + 8) * DIM + cb];
            f[2] = *(const float2*)&g_q[(size_t)row0 * DIM + cb + 8];
            f[3] = *(const float2*)&g_q[(size_t)(row0 + 8) * DIM + cb + 8];
#pragma unroll
            for (int r = 0; r < 4; r++)
                aqh[ks][r] = pack_split(f[r].x * 0.125f, f[r].y * 0.125f, &aql[ks][r]);
        }
    }

    float m0 = -1e30f, m1 = -1e30f, l0 = 0.f, l1 = 0.f;
    float o[8][4];
#pragma unroll
    for (int nt = 0; nt < 8; nt++)
#pragma unroll
        for (int r = 0; r < 4; r++) o[nt][r] = 0.f;

    int nbr = (lane & 7) + ((lane >> 4) << 3);
    int nbk = ((lane >> 3) & 1) * 16;
    int tvr = (lane & 7) + 8 * ((lane >> 3) & 1);
    int tvc = 16 * (lane >> 4);

    f_load_kv(fsm, sb, 0, 0, h, tid, kh, kl, vh, vl);
    CP_COMMIT();

    int nkt = 2 * qt + 2;
    for (int kt = 0; kt < nkt; kt++) {
        int buf = kt & 1;
        if (kt + 1 < nkt) {
            f_load_kv(fsm, sb, buf ^ 1, kt + 1, h, tid, kh, kl, vh, vl);
            CP_COMMIT();
            CP_WAIT(1);
        } else {
            CP_WAIT(0);
        }
        __syncthreads();

        if (kt * 64 <= q0 + w * 16 + 15) {     // warp not fully masked
            uint32_t stg = sb + buf * FSTG;

            float s[8][4];
#pragma unroll
            for (int nt = 0; nt < 8; nt++)
#pragma unroll
                for (int r = 0; r < 4; r++) s[nt][r] = 0.f;

#pragma unroll
            for (int t = 0; t < 3; t++) {
                uint32_t (*aq)[4] = (t == 2) ? aql : aqh;
                uint32_t kp = stg + ((t == 1) ? 8192 : 0);
#pragma unroll
                for (int ks = 0; ks < 4; ks++) {
                    uint32_t bfr[4][4];
#pragma unroll
                    for (int bt = 0; bt < 4; bt++) {
                        uint32_t off = sw128((uint32_t)((nbr + bt * 16) * 128 + ks * 32 + nbk));
                        ldsm_x4(bfr[bt], kp + off);
                    }
#pragma unroll
                    for (int nt = 0; nt < 8; nt++)
                        mma16816(s[nt], aq[ks], &bfr[nt >> 1][(nt & 1) * 2]);
                }
            }

            if (kt >= 2 * qt) {
                int r0 = q0 + w * 16 + g, r1 = r0 + 8;
                int c0 = kt * 64 + 2 * t4;
#pragma unroll
                for (int nt = 0; nt < 8; nt++) {
                    int c = c0 + nt * 8;
                    if (c     > r0) s[nt][0] = -1e30f;
                    if (c + 1 > r0) s[nt][1] = -1e30f;
                    if (c     > r1) s[nt][2] = -1e30f;
                    if (c + 1 > r1) s[nt][3] = -1e30f;
                }
            }

            float mx0 = -1e30f, mx1 = -1e30f;
#pragma unroll
            for (int nt = 0; nt < 8; nt++) {
                mx0 = fmaxf(mx0, fmaxf(s[nt][0], s[nt][1]));
                mx1 = fmaxf(mx1, fmaxf(s[nt][2], s[nt][3]));
            }
            mx0 = fmaxf(mx0, __shfl_xor_sync(0xffffffffu, mx0, 1));
            mx0 = fmaxf(mx0, __shfl_xor_sync(0xffffffffu, mx0, 2));
            mx1 = fmaxf(mx1, __shfl_xor_sync(0xffffffffu, mx1, 1));
            mx1 = fmaxf(mx1, __shfl_xor_sync(0xffffffffu, mx1, 2));
            float mn0 = fmaxf(m0, mx0), mn1 = fmaxf(m1, mx1);
            float al0 = __expf(m0 - mn0), al1 = __expf(m1 - mn1);
            float sum0 = 0.f, sum1 = 0.f;
#pragma unroll
            for (int nt = 0; nt < 8; nt++) {
                s[nt][0] = __expf(s[nt][0] - mn0);
                s[nt][1] = __expf(s[nt][1] - mn0);
                s[nt][2] = __expf(s[nt][2] - mn1);
                s[nt][3] = __expf(s[nt][3] - mn1);
                sum0 += s[nt][0] + s[nt][1];
                sum1 += s[nt][2] + s[nt][3];
            }
            sum0 += __shfl_xor_sync(0xffffffffu, sum0, 1);
            sum0 += __shfl_xor_sync(0xffffffffu, sum0, 2);
            sum1 += __shfl_xor_sync(0xffffffffu, sum1, 1);
            sum1 += __shfl_xor_sync(0xffffffffu, sum1, 2);
            l0 = l0 * al0 + sum0;  m0 = mn0;
            l1 = l1 * al1 + sum1;  m1 = mn1;
#pragma unroll
            for (int nt = 0; nt < 8; nt++) {
                o[nt][0] *= al0; o[nt][1] *= al0;
                o[nt][2] *= al1; o[nt][3] *= al1;
            }

            uint32_t ph[4][4], pl[4][4];
#pragma unroll
            for (int j = 0; j < 4; j++) {
                int u0 = 2 * j, u1 = 2 * j + 1;
                ph[j][0] = pack_split(s[u0][0], s[u0][1], &pl[j][0]);
                ph[j][1] = pack_split(s[u0][2], s[u0][3], &pl[j][1]);
                ph[j][2] = pack_split(s[u1][0], s[u1][1], &pl[j][2]);
                ph[j][3] = pack_split(s[u1][2], s[u1][3], &pl[j][3]);
            }

#pragma unroll
            for (int c = 0; c < 3; c++) {
                uint32_t (*ap)[4] = (c == 2) ? pl : ph;
                uint32_t vp = stg + 16384 + ((c == 1) ? 8192 : 0);
#pragma unroll
                for (int j = 0; j < 4; j++) {
                    uint32_t bv[4][4];
#pragma unroll
                    for (int bt = 0; bt < 4; bt++) {
                        uint32_t off = sw128((uint32_t)((j * 16 + tvr) * 128 + bt * 32 + tvc));
                        ldsm_x4_t(bv[bt], vp + off);
                    }
#pragma unroll
                    for (int nt = 0; nt < 8; nt++)
                        mma16816(o[nt], ap[j], &bv[nt >> 1][(nt & 1) * 2]);
                }
            }
        }
        __syncthreads();
    }

    // Epilogue: normalize, split to [H|H|L] directly into abig
    float i0 = 1.f / l0, i1 = 1.f / l1;
    int row0 = q0 + w * 16 + g;
#pragma unroll
    for (int nt = 0; nt < 8; nt++) {
        int col = h * HD + nt * 8 + 2 * t4;
        size_t b0 = (size_t)row0 * KE + col;
        size_t b1 = (size_t)(row0 + 8) * KE + col;
        uint32_t lo, hi;
        hi = pack_split(o[nt][0] * i0, o[nt][1] * i0, &lo);
        *(uint32_t*)&abig[b0] = hi;
        *(uint32_t*)&abig[b0 + 1024] = hi;
        *(uint32_t*)&abig[b0 + 2048] = lo;
        hi = pack_split(o[nt][2] * i1, o[nt][3] * i1, &lo);
        *(uint32_t*)&abig[b1] = hi;
        *(uint32_t*)&abig[b1 + 1024] = hi;
        *(uint32_t*)&abig[b1 + 2048] = lo;
    }
}

// v1 passthrough copy
__global__ void copy_kernel(const float4* __restrict__ src, float4* __restrict__ dst, int n4) {
    int i = blockIdx.x * blockDim.x + threadIdx.x;
    if (i < n4) dst[i] = src[i];
}

// ===========================================================================
extern "C" void kernel_launch(void* const* d_in, const int* in_sizes, int n_in,
                              void* d_out, int out_size) {
    const float* x    = (const float*)d_in[0];
    const float* v1   = (const float*)d_in[1];
    const float* Wq   = (const float*)d_in[2];
    const float* Wk   = (const float*)d_in[3];
    const float* Wv   = (const float*)d_in[4];
    const float* Wout = (const float*)d_in[5];
    const float* lam  = (const float*)d_in[6];
    float* out = (float*)d_out;

    float *q, *k, *v;
    __nv_bfloat16 *abig, *wbig;
    cudaGetSymbolAddress((void**)&q, g_q);
    cudaGetSymbolAddress((void**)&k, g_k);
    cudaGetSymbolAddress((void**)&v, g_v);
    cudaGetSymbolAddress((void**)&abig, g_abig);
    cudaGetSymbolAddress((void**)&wbig, g_wbig);

    static bool attr_set = false;
    if (!attr_set) {
        cudaFuncSetAttribute(gemm_hmma3, cudaFuncAttributeMaxDynamicSharedMemorySize, GSMEM);
        cudaFuncSetAttribute(flash_hmma, cudaFuncAttributeMaxDynamicSharedMemorySize, FSMEM);
        attr_set = true;
    }

    rope_table_kernel<<<SEQ, 32>>>();

    split_act_kernel<<<(SEQ * DIM) / 256, 256>>>(x, abig);
    split_w4_kernel<<<dim3((DIM * DIM) / 256, 4), 256>>>(Wq, Wk, Wv, Wout, wbig);

    // Fused QKV projections
    gemm_hmma3<<<dim3(DIM / TN, SEQ / TM, 3), 256, GSMEM>>>(abig, wbig, q, k, v);

    postproc_kernel<<<(SEQ * NH) / 8, 256>>>(v1, lam);

    flash_hmma<<<dim3(NH, SEQ / 128), 256, FSMEM>>>(abig);

    // Output projection
    gemm_hmma3<<<dim3(DIM / TN, SEQ / TM, 1), 256, GSMEM>>>(
        abig, wbig + 3 * (size_t)DIM * KE, out, out, out);

    if (out_size >= 2 * SEQ * DIM) {
        int n4 = (SEQ * DIM) / 4;
        copy_kernel<<<(n4 + 255) / 256, 256>>>((const float4*)v1,
                                               (float4*)(out + SEQ * DIM), n4);
    }
}